// round 4
// baseline (speedup 1.0000x reference)
#include <cuda_runtime.h>

#define NN 50000
#define NE 600000
#define DI 128
#define DH 256

// ---------------- scratch (device globals; referenced ONLY in device code) --
__device__ int g_is64;                                     // 1 if indices are int64
__device__ __align__(16) float g_dinv[NN];                 // deg, then rsqrt(deg)
__device__ __align__(16) float g_agg1[(size_t)NN * DI];    // A_norm @ x
__device__ __align__(16) float g_h[(size_t)NN * DH];       // relu(agg1@W1+b1)
__device__ __align__(16) float g_t[(size_t)NN * DI];       // h @ W2

// ---------------- index dtype detection -------------------------------------
// int64 data with values < 2^31 viewed as int32 is [lo, 0, lo, 0, ...].
__global__ void k_detect(const int* __restrict__ ei32) {
    if (threadIdx.x == 0 && blockIdx.x == 0) {
        int ok = 1;
        for (int i = 0; i < 32; i++)
            if (ei32[2 * i + 1] != 0) ok = 0;
        g_is64 = ok;
    }
}

__device__ __forceinline__ int get_idx(const void* __restrict__ base, long long i) {
    if (g_is64) return (int)((const long long*)base)[i];
    return ((const int*)base)[i];
}

// ---------------- degree / dinv --------------------------------------------
__global__ void k_deg_init() {
    int i = blockIdx.x * blockDim.x + threadIdx.x;
    if (i < NN) g_dinv[i] = 1.0f;   // self-loop weight
}

__global__ void k_deg_accum(const void* __restrict__ ei,
                            const float* __restrict__ ew) {
    int e = blockIdx.x * blockDim.x + threadIdx.x;
    if (e < NE) {
        int c = get_idx(ei, (long long)NE + e);   // col = second row of edge_index
        atomicAdd(&g_dinv[c], ew[e]);
    }
}

__global__ void k_finalize_dinv() {
    int i = blockIdx.x * blockDim.x + threadIdx.x;
    if (i < NN) g_dinv[i] = rsqrtf(g_dinv[i]);   // deg >= 1 always (self-loop)
}

// ---------------- self-loop init: dst[i,:] = dinv[i]^2 * src[i,:] ----------
// MODE 0: src = x (param),  dst = g_agg1
// MODE 1: src = g_t,        dst = out (param)
template <int MODE>
__global__ void k_self(const float* __restrict__ xp, float* __restrict__ op) {
    int idx = blockIdx.x * blockDim.x + threadIdx.x;    // over NN*DI/4
    if (idx >= NN * DI / 4) return;
    const float* src = (MODE == 0) ? xp : (const float*)g_t;
    float*       dst = (MODE == 0) ? (float*)g_agg1 : op;
    int node = idx >> 5;   // DI/4 == 32 float4 per row
    float s = g_dinv[node];
    s = s * s;
    float4 v = ((const float4*)src)[idx];
    v.x *= s; v.y *= s; v.z *= s; v.w *= s;
    ((float4*)dst)[idx] = v;
}

// ---------------- edge aggregation: dst[col,:] += norm * src[row,:] --------
// One warp per edge; lane j handles dims {j, j+32, j+64, j+96}.
// MODE 0: src = x (param),  dst = g_agg1
// MODE 1: src = g_t,        dst = out (param)
template <int MODE>
__global__ void k_edge_agg(const void* __restrict__ ei,
                           const float* __restrict__ ew,
                           const float* __restrict__ xp,
                           float* __restrict__ op) {
    int w = (blockIdx.x * blockDim.x + threadIdx.x) >> 5;
    if (w >= NE) return;
    const float* src = (MODE == 0) ? xp : (const float*)g_t;
    float*       dst = (MODE == 0) ? (float*)g_agg1 : op;
    int lane = threadIdx.x & 31;
    int r = get_idx(ei, w);
    int c = get_idx(ei, (long long)NE + w);
    float coeff = g_dinv[r] * ew[w] * g_dinv[c];
    const float* __restrict__ s = src + (size_t)r * DI;
    float* __restrict__ d = dst + (size_t)c * DI;
#pragma unroll
    for (int j = 0; j < 4; j++) {
        int dd = lane + 32 * j;
        atomicAdd(d + dd, coeff * s[dd]);
    }
}

// ---------------- tiled SGEMM ------------------------------------------------
// MODE 0 (layer 1): C[g_h] = relu(A[g_agg1][NN,DI] @ B[DI,DH] + bias)
// MODE 1 (layer 2): C[g_t] = A[g_h][NN,DH] @ B[DH,DI]
// BM=BN=128, BK=16, 256 threads, 8x8 micro-tile per thread.
template <int MODE>
__global__ void __launch_bounds__(256)
k_gemm(const float* __restrict__ B, const float* __restrict__ bias) {
    constexpr int K = (MODE == 0) ? DI : DH;
    constexpr int N = (MODE == 0) ? DH : DI;
    constexpr int M = NN;
    const float* A = (MODE == 0) ? (const float*)g_agg1 : (const float*)g_h;
    float*       C = (MODE == 0) ? (float*)g_h : (float*)g_t;

    constexpr int BM = 128, BN = 128, BK = 16;
    __shared__ float As[BK][BM + 4];
    __shared__ float Bs[BK][BN + 4];

    int tid = threadIdx.x;
    int tx = tid & 15;        // 0..15 -> 8 output cols each
    int ty = tid >> 4;        // 0..15 -> 8 output rows each
    int rowBase = blockIdx.y * BM;
    int colBase = blockIdx.x * BN;

    float acc[8][8];
#pragma unroll
    for (int i = 0; i < 8; i++)
#pragma unroll
        for (int j = 0; j < 8; j++) acc[i][j] = 0.0f;

    for (int k0 = 0; k0 < K; k0 += BK) {
        // load A tile (transposed into As[k][m]); M-edge guarded
#pragma unroll
        for (int p = 0; p < 2; p++) {
            int idx = tid + p * 256;       // 0..511
            int m  = idx >> 2;             // 0..127
            int k4 = (idx & 3) * 4;        // 0,4,8,12
            int gr = rowBase + m;
            float4 v = make_float4(0.f, 0.f, 0.f, 0.f);
            if (gr < M) v = *(const float4*)(A + (size_t)gr * K + k0 + k4);
            As[k4 + 0][m] = v.x;
            As[k4 + 1][m] = v.y;
            As[k4 + 2][m] = v.z;
            As[k4 + 3][m] = v.w;
        }
        // load B tile (direct)
#pragma unroll
        for (int p = 0; p < 2; p++) {
            int idx = tid + p * 256;       // 0..511
            int kk = idx >> 5;             // 0..15
            int n4 = (idx & 31) * 4;       // 0..124
            float4 v = *(const float4*)(B + (size_t)(k0 + kk) * N + colBase + n4);
            *(float4*)&Bs[kk][n4] = v;
        }
        __syncthreads();

#pragma unroll
        for (int kk = 0; kk < BK; kk++) {
            float a[8], b[8];
            *(float4*)&a[0] = *(const float4*)&As[kk][ty * 8];
            *(float4*)&a[4] = *(const float4*)&As[kk][ty * 8 + 4];
            *(float4*)&b[0] = *(const float4*)&Bs[kk][tx * 8];
            *(float4*)&b[4] = *(const float4*)&Bs[kk][tx * 8 + 4];
#pragma unroll
            for (int i = 0; i < 8; i++)
#pragma unroll
                for (int j = 0; j < 8; j++)
                    acc[i][j] = fmaf(a[i], b[j], acc[i][j]);
        }
        __syncthreads();
    }

    // epilogue
#pragma unroll
    for (int i = 0; i < 8; i++) {
        int r = rowBase + ty * 8 + i;
        if (r >= M) continue;
#pragma unroll
        for (int j4 = 0; j4 < 2; j4++) {
            int c = colBase + tx * 8 + j4 * 4;
            float4 v;
            v.x = acc[i][j4 * 4 + 0];
            v.y = acc[i][j4 * 4 + 1];
            v.z = acc[i][j4 * 4 + 2];
            v.w = acc[i][j4 * 4 + 3];
            if (MODE == 0) {
                float4 bv = *(const float4*)(bias + c);
                v.x = fmaxf(v.x + bv.x, 0.f);
                v.y = fmaxf(v.y + bv.y, 0.f);
                v.z = fmaxf(v.z + bv.z, 0.f);
                v.w = fmaxf(v.w + bv.w, 0.f);
            }
            *(float4*)(C + (size_t)r * N + c) = v;
        }
    }
}

// ---------------- final: out = relu(out + b2) ------------------------------
__global__ void k_bias_relu(float* __restrict__ out, const float* __restrict__ b) {
    int idx = blockIdx.x * blockDim.x + threadIdx.x;    // over NN*DI/4
    if (idx >= NN * DI / 4) return;
    int c4 = (idx & 31) * 4;
    float4 bv = *(const float4*)(b + c4);
    float4 v = ((float4*)out)[idx];
    v.x = fmaxf(v.x + bv.x, 0.f);
    v.y = fmaxf(v.y + bv.y, 0.f);
    v.z = fmaxf(v.z + bv.z, 0.f);
    v.w = fmaxf(v.w + bv.w, 0.f);
    ((float4*)out)[idx] = v;
}

// ---------------- launch ----------------------------------------------------
extern "C" void kernel_launch(void* const* d_in, const int* in_sizes, int n_in,
                              void* d_out, int out_size) {
    const float* x   = (const float*)d_in[0];
    const void*  ei  = d_in[1];                 // [2, NE], int32 or int64
    const float* ew  = (const float*)d_in[2];
    const float* W1  = (const float*)d_in[3];
    const float* b1  = (const float*)d_in[4];
    const float* W2  = (const float*)d_in[5];
    const float* b2  = (const float*)d_in[6];
    float*       out = (float*)d_out;

    const int TB = 256;
    int nbN  = (NN + TB - 1) / TB;
    int nbE  = (NE + TB - 1) / TB;
    int nbF  = (NN * DI / 4 + TB - 1) / TB;
    long long nEW = (long long)NE * 32;
    int nbEW = (int)((nEW + TB - 1) / TB);

    // index dtype detection (device-side, deterministic)
    k_detect<<<1, 32>>>((const int*)ei);

    // degree + dinv (shared by both layers)
    k_deg_init<<<nbN, TB>>>();
    k_deg_accum<<<nbE, TB>>>(ei, ew);
    k_finalize_dinv<<<nbN, TB>>>();

    // layer 1: g_agg1 = A_norm @ x ; g_h = relu(g_agg1 @ W1 + b1)
    k_self<0><<<nbF, TB>>>(x, nullptr);
    k_edge_agg<0><<<nbEW, TB>>>(ei, ew, x, nullptr);
    k_gemm<0><<<dim3(DH / 128, (NN + 127) / 128), TB>>>(W1, b1);

    // layer 2: g_t = g_h @ W2 ; out = relu(A_norm @ g_t + b2)
    k_gemm<1><<<dim3(DI / 128, (NN + 127) / 128), TB>>>(W2, nullptr);
    k_self<1><<<nbF, TB>>>(nullptr, out);
    k_edge_agg<1><<<nbEW, TB>>>(ei, ew, nullptr, out);
    k_bias_relu<<<nbF, TB>>>(out, b2);
}

// round 7
// speedup vs baseline: 1.2502x; 1.2502x over previous
#include <cuda_runtime.h>
#include <cuda_bf16.h>
#include <cstdint>

#define NN 50000
#define NE 600000
#define DI 128
#define DH 256

// ---------------- scratch (device globals; referenced ONLY in device code) --
__device__ int g_is64;                                     // 1 if indices are int64
__device__ __align__(16) float g_dinv[NN];                 // deg, then rsqrt(deg)
__device__ __align__(16) float g_agg1[(size_t)NN * DI];    // A_norm @ x
__device__ __align__(16) float g_h[(size_t)NN * DH];       // relu(agg1@W1+b1)
__device__ __align__(16) float g_t[(size_t)NN * DI];       // h @ W2

__device__ __forceinline__ uint32_t smem_u32(const void* p) {
    return (uint32_t)__cvta_generic_to_shared(p);
}

// ---------------- index dtype detection -------------------------------------
__global__ void k_detect(const int* __restrict__ ei32) {
    if (threadIdx.x == 0 && blockIdx.x == 0) {
        int ok = 1;
        for (int i = 0; i < 32; i++)
            if (ei32[2 * i + 1] != 0) ok = 0;
        g_is64 = ok;
    }
}

__device__ __forceinline__ int get_idx(const void* __restrict__ base, long long i) {
    if (g_is64) return (int)((const long long*)base)[i];
    return ((const int*)base)[i];
}

// ---------------- degree / dinv --------------------------------------------
__global__ void k_deg_init() {
    int i = blockIdx.x * blockDim.x + threadIdx.x;
    if (i < NN) g_dinv[i] = 1.0f;
}

__global__ void k_deg_accum(const void* __restrict__ ei, const float* __restrict__ ew) {
    int e = blockIdx.x * blockDim.x + threadIdx.x;
    if (e < NE) {
        int c = get_idx(ei, (long long)NE + e);
        atomicAdd(&g_dinv[c], ew[e]);
    }
}

__global__ void k_finalize_dinv() {
    int i = blockIdx.x * blockDim.x + threadIdx.x;
    if (i < NN) g_dinv[i] = rsqrtf(g_dinv[i]);
}

// ---------------- self-loop init: dst[i,:] = dinv[i]^2 * src[i,:] ----------
template <int MODE>
__global__ void k_self(const float* __restrict__ xp, float* __restrict__ op) {
    int idx = blockIdx.x * blockDim.x + threadIdx.x;
    if (idx >= NN * DI / 4) return;
    const float* src = (MODE == 0) ? xp : (const float*)g_t;
    float*       dst = (MODE == 0) ? (float*)g_agg1 : op;
    int node = idx >> 5;
    float s = g_dinv[node];
    s = s * s;
    float4 v = ((const float4*)src)[idx];
    v.x *= s; v.y *= s; v.z *= s; v.w *= s;
    ((float4*)dst)[idx] = v;
}

// ---------------- edge aggregation ------------------------------------------
template <int MODE>
__global__ void k_edge_agg(const void* __restrict__ ei, const float* __restrict__ ew,
                           const float* __restrict__ xp, float* __restrict__ op) {
    int w = (blockIdx.x * blockDim.x + threadIdx.x) >> 5;
    if (w >= NE) return;
    const float* src = (MODE == 0) ? xp : (const float*)g_t;
    float*       dst = (MODE == 0) ? (float*)g_agg1 : op;
    int lane = threadIdx.x & 31;
    int r = get_idx(ei, w);
    int c = get_idx(ei, (long long)NE + w);
    float coeff = g_dinv[r] * ew[w] * g_dinv[c];
    const float* __restrict__ s = src + (size_t)r * DI;
    float* __restrict__ d = dst + (size_t)c * DI;
#pragma unroll
    for (int j = 0; j < 4; j++) {
        int dd = lane + 32 * j;
        atomicAdd(d + dd, coeff * s[dd]);
    }
}

// =================== tensor-core GEMM (mma.sync, bf16 3-way split) ==========
// MODE 0: C[g_h] = relu(g_agg1[NN,128] @ W1[128,256] + b1)
// MODE 1: C[g_t] =       g_h[NN,256] @ W2[256,128]
// Block 128x128, 8 warps (2 M x 4 N), warp tile 64x32, m16n8k16 bf16->fp32.
// D = Ahi@Bhi + Ahi@Blo + Alo@Bhi (fp32 accum in registers).

__device__ __forceinline__ void ldsm_x4(uint32_t* r, uint32_t addr) {
    asm volatile("ldmatrix.sync.aligned.m8n8.x4.shared.b16 {%0,%1,%2,%3}, [%4];"
                 : "=r"(r[0]), "=r"(r[1]), "=r"(r[2]), "=r"(r[3]) : "r"(addr));
}

__device__ __forceinline__ void mma16816(float* c, const uint32_t* a, const uint32_t* b) {
    asm volatile(
        "mma.sync.aligned.m16n8k16.row.col.f32.bf16.bf16.f32 "
        "{%0,%1,%2,%3}, {%4,%5,%6,%7}, {%8,%9}, {%0,%1,%2,%3};"
        : "+f"(c[0]), "+f"(c[1]), "+f"(c[2]), "+f"(c[3])
        : "r"(a[0]), "r"(a[1]), "r"(a[2]), "r"(a[3]), "r"(b[0]), "r"(b[1]));
}

#define BK 64
#define SA 72   // bf16 row stride (BK + 8): 144B rows -> conflict-free ldmatrix
#define SMEM_MM (4 * 128 * SA * 2)   // Ah, Al, Bh, Bl = 73728 B

template <int MODE>
__global__ void __launch_bounds__(256)
k_mm(const float* __restrict__ W, const float* __restrict__ bias) {
    constexpr int Kdim = (MODE == 0) ? DI : DH;
    constexpr int Ndim = (MODE == 0) ? DH : DI;
    const float* A = (MODE == 0) ? (const float*)g_agg1 : (const float*)g_h;
    float*       C = (MODE == 0) ? (float*)g_h : (float*)g_t;

    extern __shared__ __nv_bfloat16 sm[];
    __nv_bfloat16* Ah = sm;
    __nv_bfloat16* Al = sm + 128 * SA;
    __nv_bfloat16* Bh = sm + 2 * 128 * SA;
    __nv_bfloat16* Bl = sm + 3 * 128 * SA;

    int tid = threadIdx.x, lane = tid & 31, wid = tid >> 5;
    int mw = wid >> 2, nw = wid & 3;           // warp coords: 2 x 4
    int rowBase = blockIdx.y * 128;
    int n0 = blockIdx.x * 128;

    float acc[4][4][4];
#pragma unroll
    for (int i = 0; i < 4; i++)
#pragma unroll
        for (int j = 0; j < 4; j++)
#pragma unroll
            for (int q = 0; q < 4; q++) acc[i][j][q] = 0.0f;

    uint32_t smbA = smem_u32(Ah);
    uint32_t smbAl = smem_u32(Al);
    uint32_t smbB = smem_u32(Bh);
    uint32_t smbBl = smem_u32(Bl);

    // lane-invariant parts of fragment addresses
    int a_row_l = ((lane >> 3) & 1) * 8 + (lane & 7);
    int a_k_l   = (lane >> 4) * 8;
    int b_n_l   = (lane >> 4) * 8 + (lane & 7);
    int b_k_l   = ((lane >> 3) & 1) * 8;

    for (int ch = 0; ch < Kdim / BK; ch++) {
        int k0 = ch * BK;
        if (ch) __syncthreads();
        // ---- fill A (hi/lo split), [128][BK] ----
#pragma unroll
        for (int it = 0; it < 8; it++) {
            int idx = it * 256 + tid;          // 2048 float4
            int r  = idx >> 4;
            int c4 = (idx & 15) * 4;
            int gr = rowBase + r;
            float4 v = make_float4(0.f, 0.f, 0.f, 0.f);
            if (gr < NN) v = *(const float4*)(A + (size_t)gr * Kdim + k0 + c4);
            __nv_bfloat16 hx = __float2bfloat16_rn(v.x);
            __nv_bfloat16 hy = __float2bfloat16_rn(v.y);
            __nv_bfloat16 hz = __float2bfloat16_rn(v.z);
            __nv_bfloat16 hw = __float2bfloat16_rn(v.w);
            __nv_bfloat16 lx = __float2bfloat16_rn(v.x - __bfloat162float(hx));
            __nv_bfloat16 ly = __float2bfloat16_rn(v.y - __bfloat162float(hy));
            __nv_bfloat16 lz = __float2bfloat16_rn(v.z - __bfloat162float(hz));
            __nv_bfloat16 lw = __float2bfloat16_rn(v.w - __bfloat162float(hw));
            int o = r * SA + c4;
            *(__nv_bfloat162*)(Ah + o)     = __halves2bfloat162(hx, hy);
            *(__nv_bfloat162*)(Ah + o + 2) = __halves2bfloat162(hz, hw);
            *(__nv_bfloat162*)(Al + o)     = __halves2bfloat162(lx, ly);
            *(__nv_bfloat162*)(Al + o + 2) = __halves2bfloat162(lz, lw);
        }
        // ---- fill B (hi/lo split), stored [n][k] ----
#pragma unroll
        for (int it = 0; it < 32; it++) {
            int idx = it * 256 + tid;          // 8192 = BK x 128
            int k = idx >> 7;
            int n = idx & 127;
            float w = W[(size_t)(k0 + k) * Ndim + n0 + n];
            __nv_bfloat16 h = __float2bfloat16_rn(w);
            __nv_bfloat16 l = __float2bfloat16_rn(w - __bfloat162float(h));
            Bh[n * SA + k] = h;
            Bl[n * SA + k] = l;
        }
        __syncthreads();

        // ---- 4 K-steps of 16 ----
#pragma unroll
        for (int s = 0; s < 4; s++) {
            uint32_t aH[4][4], aL[4][4], bH[2][4], bL[2][4];
#pragma unroll
            for (int i = 0; i < 4; i++) {
                int row = mw * 64 + i * 16 + a_row_l;
                int kk  = s * 16 + a_k_l;
                uint32_t off = (uint32_t)(row * SA + kk) * 2;
                ldsm_x4(aH[i], smbA + off);
                ldsm_x4(aL[i], smbAl + off);
            }
#pragma unroll
            for (int p = 0; p < 2; p++) {
                int n = nw * 32 + p * 16 + b_n_l;
                int kk = s * 16 + b_k_l;
                uint32_t off = (uint32_t)(n * SA + kk) * 2;
                ldsm_x4(bH[p], smbB + off);
                ldsm_x4(bL[p], smbBl + off);
            }
#pragma unroll
            for (int i = 0; i < 4; i++)
#pragma unroll
                for (int j = 0; j < 4; j++) {
                    int p = j >> 1, o = (j & 1) * 2;
                    mma16816(acc[i][j], aH[i], &bH[p][o]);
                    mma16816(acc[i][j], aH[i], &bL[p][o]);
                    mma16816(acc[i][j], aL[i], &bH[p][o]);
                }
        }
    }

    // ---- epilogue ----
#pragma unroll
    for (int i = 0; i < 4; i++) {
        int r0 = rowBase + mw * 64 + i * 16 + (lane >> 2);
#pragma unroll
        for (int j = 0; j < 4; j++) {
            int gc = n0 + nw * 32 + j * 8 + (lane & 3) * 2;
            float2 v0 = make_float2(acc[i][j][0], acc[i][j][1]);
            float2 v1 = make_float2(acc[i][j][2], acc[i][j][3]);
            if (MODE == 0) {
                float2 bv = *(const float2*)(bias + gc);
                v0.x = fmaxf(v0.x + bv.x, 0.f);
                v0.y = fmaxf(v0.y + bv.y, 0.f);
                v1.x = fmaxf(v1.x + bv.x, 0.f);
                v1.y = fmaxf(v1.y + bv.y, 0.f);
            }
            if (r0 < NN)     *(float2*)(C + (size_t)r0 * Ndim + gc)       = v0;
            if (r0 + 8 < NN) *(float2*)(C + (size_t)(r0 + 8) * Ndim + gc) = v1;
        }
    }
}

// ---------------- final: out = relu(out + b2) ------------------------------
__global__ void k_bias_relu(float* __restrict__ out, const float* __restrict__ b) {
    int idx = blockIdx.x * blockDim.x + threadIdx.x;
    if (idx >= NN * DI / 4) return;
    int c4 = (idx & 31) * 4;
    float4 bv = *(const float4*)(b + c4);
    float4 v = ((float4*)out)[idx];
    v.x = fmaxf(v.x + bv.x, 0.f);
    v.y = fmaxf(v.y + bv.y, 0.f);
    v.z = fmaxf(v.z + bv.z, 0.f);
    v.w = fmaxf(v.w + bv.w, 0.f);
    ((float4*)out)[idx] = v;
}

// ---------------- launch ----------------------------------------------------
extern "C" void kernel_launch(void* const* d_in, const int* in_sizes, int n_in,
                              void* d_out, int out_size) {
    const float* x   = (const float*)d_in[0];
    const void*  ei  = d_in[1];                 // [2, NE], int32 or int64
    const float* ew  = (const float*)d_in[2];
    const float* W1  = (const float*)d_in[3];
    const float* b1  = (const float*)d_in[4];
    const float* W2  = (const float*)d_in[5];
    const float* b2  = (const float*)d_in[6];
    float*       out = (float*)d_out;

    static bool attr_done = false;
    if (!attr_done) {
        cudaFuncSetAttribute(k_mm<0>, cudaFuncAttributeMaxDynamicSharedMemorySize, SMEM_MM);
        cudaFuncSetAttribute(k_mm<1>, cudaFuncAttributeMaxDynamicSharedMemorySize, SMEM_MM);
        attr_done = true;
    }

    const int TB = 256;
    int nbN  = (NN + TB - 1) / TB;
    int nbE  = (NE + TB - 1) / TB;
    int nbF  = (NN * DI / 4 + TB - 1) / TB;
    long long nEW = (long long)NE * 32;
    int nbEW = (int)((nEW + TB - 1) / TB);
    int nbM  = (NN + 127) / 128;

    k_detect<<<1, 32>>>((const int*)ei);

    // degree + dinv (shared by both layers)
    k_deg_init<<<nbN, TB>>>();
    k_deg_accum<<<nbE, TB>>>(ei, ew);
    k_finalize_dinv<<<nbN, TB>>>();

    // layer 1: g_agg1 = A_norm @ x ; g_h = relu(g_agg1 @ W1 + b1)
    k_self<0><<<nbF, TB>>>(x, nullptr);
    k_edge_agg<0><<<nbEW, TB>>>(ei, ew, x, nullptr);
    k_mm<0><<<dim3(2, nbM), TB, SMEM_MM>>>(W1, b1);

    // layer 2: g_t = g_h @ W2 ; out = relu(A_norm @ g_t + b2)
    k_mm<1><<<dim3(1, nbM), TB, SMEM_MM>>>(W2, nullptr);
    k_self<1><<<nbF, TB>>>(nullptr, out);
    k_edge_agg<1><<<nbEW, TB>>>(ei, ew, nullptr, out);
    k_bias_relu<<<nbF, TB>>>(out, b2);
}

// round 8
// speedup vs baseline: 1.4159x; 1.1326x over previous
#include <cuda_runtime.h>
#include <cuda_bf16.h>
#include <cstdint>

#define NN 50000
#define NE 600000
#define DI 128
#define DH 256

// ---------------- scratch (device globals; referenced ONLY in device code) --
__device__ int g_is64;                                     // 1 if indices are int64
__device__ __align__(16) float g_dinv[NN];                 // deg, then rsqrt(deg)
__device__ __align__(16) int2  g_rc[NE];                   // packed (row, col)
__device__ __align__(16) float g_coeff[NE];                // dinv[r]*ew*dinv[c]
__device__ __align__(16) float g_agg1[(size_t)NN * DI];    // A_norm @ x
__device__ __align__(16) float g_h[(size_t)NN * DH];       // relu(agg1@W1+b1)
__device__ __align__(16) float g_t[(size_t)NN * DI];       // h @ W2

__device__ __forceinline__ uint32_t smem_u32(const void* p) {
    return (uint32_t)__cvta_generic_to_shared(p);
}

// ---------------- index dtype detection -------------------------------------
__global__ void k_detect(const int* __restrict__ ei32) {
    if (threadIdx.x == 0 && blockIdx.x == 0) {
        int ok = 1;
        for (int i = 0; i < 32; i++)
            if (ei32[2 * i + 1] != 0) ok = 0;
        g_is64 = ok;
    }
}

__device__ __forceinline__ int get_idx(const void* __restrict__ base, long long i) {
    if (g_is64) return (int)((const long long*)base)[i];
    return ((const int*)base)[i];
}

// ---------------- degree / dinv --------------------------------------------
__global__ void k_deg_init() {
    int i = blockIdx.x * blockDim.x + threadIdx.x;
    if (i < NN) g_dinv[i] = 1.0f;
}

__global__ void k_deg_accum(const void* __restrict__ ei, const float* __restrict__ ew) {
    int e = blockIdx.x * blockDim.x + threadIdx.x;
    if (e < NE) {
        int c = get_idx(ei, (long long)NE + e);
        atomicAdd(&g_dinv[c], ew[e]);
    }
}

__global__ void k_finalize_dinv() {
    int i = blockIdx.x * blockDim.x + threadIdx.x;
    if (i < NN) g_dinv[i] = rsqrtf(g_dinv[i]);
}

// ---------------- per-edge precompute: rc + coeff ---------------------------
__global__ void k_prep(const void* __restrict__ ei, const float* __restrict__ ew) {
    int e = blockIdx.x * blockDim.x + threadIdx.x;
    if (e >= NE) return;
    int r = get_idx(ei, e);
    int c = get_idx(ei, (long long)NE + e);
    g_rc[e] = make_int2(r, c);
    g_coeff[e] = g_dinv[r] * ew[e] * g_dinv[c];
}

// ---------------- self-loop init: dst[i,:] = dinv[i]^2 * src[i,:] ----------
template <int MODE>
__global__ void k_self(const float* __restrict__ xp, float* __restrict__ op) {
    int idx = blockIdx.x * blockDim.x + threadIdx.x;
    if (idx >= NN * DI / 4) return;
    const float* src = (MODE == 0) ? xp : (const float*)g_t;
    float*       dst = (MODE == 0) ? (float*)g_agg1 : op;
    int node = idx >> 5;
    float s = g_dinv[node];
    s = s * s;
    float4 v = ((const float4*)src)[idx];
    v.x *= s; v.y *= s; v.z *= s; v.w *= s;
    ((float4*)dst)[idx] = v;
}

// ---------------- edge aggregation: dst[col,:] += coeff * src[row,:] --------
// One warp per edge; lane j handles float4 j (128 floats = 32 float4).
// 1 LDG.128 + 1 red.global.add.v4.f32 per lane.
template <int MODE>
__global__ void k_edge_agg(const float* __restrict__ xp, float* __restrict__ op) {
    int w = (blockIdx.x * blockDim.x + threadIdx.x) >> 5;
    if (w >= NE) return;
    const float* src = (MODE == 0) ? xp : (const float*)g_t;
    float*       dst = (MODE == 0) ? (float*)g_agg1 : op;
    int lane = threadIdx.x & 31;
    int2 rc = g_rc[w];
    float coeff = g_coeff[w];
    float4 v = ((const float4*)(src + (size_t)rc.x * DI))[lane];
    v.x *= coeff; v.y *= coeff; v.z *= coeff; v.w *= coeff;
    float* d = dst + (size_t)rc.y * DI + lane * 4;
    asm volatile("red.global.add.v4.f32 [%0], {%1, %2, %3, %4};"
                 :: "l"(d), "f"(v.x), "f"(v.y), "f"(v.z), "f"(v.w)
                 : "memory");
}

// =================== tensor-core GEMM (mma.sync, bf16 3-way split) ==========
// MODE 0: C[g_h] = relu(g_agg1[NN,128] @ W1[128,256] + b1)
// MODE 1: C[g_t] =       g_h[NN,256] @ W2[256,128]
// Block 128x128, 8 warps (2 M x 4 N), warp tile 64x32, m16n8k16 bf16->fp32.
// D = Ahi@Bhi + Ahi@Blo + Alo@Bhi (fp32 accum in registers).

__device__ __forceinline__ void ldsm_x4(uint32_t* r, uint32_t addr) {
    asm volatile("ldmatrix.sync.aligned.m8n8.x4.shared.b16 {%0,%1,%2,%3}, [%4];"
                 : "=r"(r[0]), "=r"(r[1]), "=r"(r[2]), "=r"(r[3]) : "r"(addr));
}

__device__ __forceinline__ void mma16816(float* c, const uint32_t* a, const uint32_t* b) {
    asm volatile(
        "mma.sync.aligned.m16n8k16.row.col.f32.bf16.bf16.f32 "
        "{%0,%1,%2,%3}, {%4,%5,%6,%7}, {%8,%9}, {%0,%1,%2,%3};"
        : "+f"(c[0]), "+f"(c[1]), "+f"(c[2]), "+f"(c[3])
        : "r"(a[0]), "r"(a[1]), "r"(a[2]), "r"(a[3]), "r"(b[0]), "r"(b[1]));
}

#define BK 64
#define SA 72   // bf16 row stride (BK + 8): 144B rows -> conflict-free ldmatrix
#define SMEM_MM (4 * 128 * SA * 2)   // Ah, Al, Bh, Bl = 73728 B

template <int MODE>
__global__ void __launch_bounds__(256)
k_mm(const float* __restrict__ W, const float* __restrict__ bias) {
    constexpr int Kdim = (MODE == 0) ? DI : DH;
    constexpr int Ndim = (MODE == 0) ? DH : DI;
    const float* A = (MODE == 0) ? (const float*)g_agg1 : (const float*)g_h;
    float*       C = (MODE == 0) ? (float*)g_h : (float*)g_t;

    extern __shared__ __nv_bfloat16 sm[];
    __nv_bfloat16* Ah = sm;
    __nv_bfloat16* Al = sm + 128 * SA;
    __nv_bfloat16* Bh = sm + 2 * 128 * SA;
    __nv_bfloat16* Bl = sm + 3 * 128 * SA;

    int tid = threadIdx.x, lane = tid & 31, wid = tid >> 5;
    int mw = wid >> 2, nw = wid & 3;           // warp coords: 2 x 4
    int rowBase = blockIdx.y * 128;
    int n0 = blockIdx.x * 128;

    float acc[4][4][4];
#pragma unroll
    for (int i = 0; i < 4; i++)
#pragma unroll
        for (int j = 0; j < 4; j++)
#pragma unroll
            for (int q = 0; q < 4; q++) acc[i][j][q] = 0.0f;

    uint32_t smbA = smem_u32(Ah);
    uint32_t smbAl = smem_u32(Al);
    uint32_t smbB = smem_u32(Bh);
    uint32_t smbBl = smem_u32(Bl);

    int a_row_l = ((lane >> 3) & 1) * 8 + (lane & 7);
    int a_k_l   = (lane >> 4) * 8;
    int b_n_l   = (lane >> 4) * 8 + (lane & 7);
    int b_k_l   = ((lane >> 3) & 1) * 8;

    for (int ch = 0; ch < Kdim / BK; ch++) {
        int k0 = ch * BK;
        if (ch) __syncthreads();
        // ---- fill A (hi/lo split), [128][BK] ----
#pragma unroll
        for (int it = 0; it < 8; it++) {
            int idx = it * 256 + tid;          // 2048 float4
            int r  = idx >> 4;
            int c4 = (idx & 15) * 4;
            int gr = rowBase + r;
            float4 v = make_float4(0.f, 0.f, 0.f, 0.f);
            if (gr < NN) v = *(const float4*)(A + (size_t)gr * Kdim + k0 + c4);
            __nv_bfloat16 hx = __float2bfloat16_rn(v.x);
            __nv_bfloat16 hy = __float2bfloat16_rn(v.y);
            __nv_bfloat16 hz = __float2bfloat16_rn(v.z);
            __nv_bfloat16 hw = __float2bfloat16_rn(v.w);
            __nv_bfloat16 lx = __float2bfloat16_rn(v.x - __bfloat162float(hx));
            __nv_bfloat16 ly = __float2bfloat16_rn(v.y - __bfloat162float(hy));
            __nv_bfloat16 lz = __float2bfloat16_rn(v.z - __bfloat162float(hz));
            __nv_bfloat16 lw = __float2bfloat16_rn(v.w - __bfloat162float(hw));
            int o = r * SA + c4;
            *(__nv_bfloat162*)(Ah + o)     = __halves2bfloat162(hx, hy);
            *(__nv_bfloat162*)(Ah + o + 2) = __halves2bfloat162(hz, hw);
            *(__nv_bfloat162*)(Al + o)     = __halves2bfloat162(lx, ly);
            *(__nv_bfloat162*)(Al + o + 2) = __halves2bfloat162(lz, lw);
        }
        // ---- fill B (hi/lo split), stored [n][k] ----
#pragma unroll
        for (int it = 0; it < 32; it++) {
            int idx = it * 256 + tid;          // 8192 = BK x 128
            int k = idx >> 7;
            int n = idx & 127;
            float w = W[(size_t)(k0 + k) * Ndim + n0 + n];
            __nv_bfloat16 h = __float2bfloat16_rn(w);
            __nv_bfloat16 l = __float2bfloat16_rn(w - __bfloat162float(h));
            Bh[n * SA + k] = h;
            Bl[n * SA + k] = l;
        }
        __syncthreads();

        // ---- 4 K-steps of 16 ----
#pragma unroll
        for (int s = 0; s < 4; s++) {
            uint32_t aH[4][4], aL[4][4], bH[2][4], bL[2][4];
#pragma unroll
            for (int i = 0; i < 4; i++) {
                int row = mw * 64 + i * 16 + a_row_l;
                int kk  = s * 16 + a_k_l;
                uint32_t off = (uint32_t)(row * SA + kk) * 2;
                ldsm_x4(aH[i], smbA + off);
                ldsm_x4(aL[i], smbAl + off);
            }
#pragma unroll
            for (int p = 0; p < 2; p++) {
                int n = nw * 32 + p * 16 + b_n_l;
                int kk = s * 16 + b_k_l;
                uint32_t off = (uint32_t)(n * SA + kk) * 2;
                ldsm_x4(bH[p], smbB + off);
                ldsm_x4(bL[p], smbBl + off);
            }
#pragma unroll
            for (int i = 0; i < 4; i++)
#pragma unroll
                for (int j = 0; j < 4; j++) {
                    int p = j >> 1, o = (j & 1) * 2;
                    mma16816(acc[i][j], aH[i], &bH[p][o]);
                    mma16816(acc[i][j], aH[i], &bL[p][o]);
                    mma16816(acc[i][j], aL[i], &bH[p][o]);
                }
        }
    }

    // ---- epilogue ----
#pragma unroll
    for (int i = 0; i < 4; i++) {
        int r0 = rowBase + mw * 64 + i * 16 + (lane >> 2);
#pragma unroll
        for (int j = 0; j < 4; j++) {
            int gc = n0 + nw * 32 + j * 8 + (lane & 3) * 2;
            float2 v0 = make_float2(acc[i][j][0], acc[i][j][1]);
            float2 v1 = make_float2(acc[i][j][2], acc[i][j][3]);
            if (MODE == 0) {
                float2 bv = *(const float2*)(bias + gc);
                v0.x = fmaxf(v0.x + bv.x, 0.f);
                v0.y = fmaxf(v0.y + bv.y, 0.f);
                v1.x = fmaxf(v1.x + bv.x, 0.f);
                v1.y = fmaxf(v1.y + bv.y, 0.f);
            }
            if (r0 < NN)     *(float2*)(C + (size_t)r0 * Ndim + gc)       = v0;
            if (r0 + 8 < NN) *(float2*)(C + (size_t)(r0 + 8) * Ndim + gc) = v1;
        }
    }
}

// ---------------- final: out = relu(out + b2) ------------------------------
__global__ void k_bias_relu(float* __restrict__ out, const float* __restrict__ b) {
    int idx = blockIdx.x * blockDim.x + threadIdx.x;
    if (idx >= NN * DI / 4) return;
    int c4 = (idx & 31) * 4;
    float4 bv = *(const float4*)(b + c4);
    float4 v = ((float4*)out)[idx];
    v.x = fmaxf(v.x + bv.x, 0.f);
    v.y = fmaxf(v.y + bv.y, 0.f);
    v.z = fmaxf(v.z + bv.z, 0.f);
    v.w = fmaxf(v.w + bv.w, 0.f);
    ((float4*)out)[idx] = v;
}

// ---------------- launch ----------------------------------------------------
extern "C" void kernel_launch(void* const* d_in, const int* in_sizes, int n_in,
                              void* d_out, int out_size) {
    const float* x   = (const float*)d_in[0];
    const void*  ei  = d_in[1];                 // [2, NE], int32 or int64
    const float* ew  = (const float*)d_in[2];
    const float* W1  = (const float*)d_in[3];
    const float* b1  = (const float*)d_in[4];
    const float* W2  = (const float*)d_in[5];
    const float* b2  = (const float*)d_in[6];
    float*       out = (float*)d_out;

    static bool attr_done = false;
    if (!attr_done) {
        cudaFuncSetAttribute(k_mm<0>, cudaFuncAttributeMaxDynamicSharedMemorySize, SMEM_MM);
        cudaFuncSetAttribute(k_mm<1>, cudaFuncAttributeMaxDynamicSharedMemorySize, SMEM_MM);
        attr_done = true;
    }

    const int TB = 256;
    int nbN  = (NN + TB - 1) / TB;
    int nbE  = (NE + TB - 1) / TB;
    int nbF  = (NN * DI / 4 + TB - 1) / TB;
    long long nEW = (long long)NE * 32;
    int nbEW = (int)((nEW + TB - 1) / TB);
    int nbM  = (NN + 127) / 128;

    k_detect<<<1, 32>>>((const int*)ei);

    // degree + dinv + per-edge coeffs (shared by both layers)
    k_deg_init<<<nbN, TB>>>();
    k_deg_accum<<<nbE, TB>>>(ei, ew);
    k_finalize_dinv<<<nbN, TB>>>();
    k_prep<<<nbE, TB>>>(ei, ew);

    // layer 1: g_agg1 = A_norm @ x ; g_h = relu(g_agg1 @ W1 + b1)
    k_self<0><<<nbF, TB>>>(x, nullptr);
    k_edge_agg<0><<<nbEW, TB>>>(x, nullptr);
    k_mm<0><<<dim3(2, nbM), TB, SMEM_MM>>>(W1, b1);

    // layer 2: g_t = g_h @ W2 ; out = relu(A_norm @ g_t + b2)
    k_mm<1><<<dim3(1, nbM), TB, SMEM_MM>>>(W2, nullptr);
    k_self<1><<<nbF, TB>>>(nullptr, out);
    k_edge_agg<1><<<nbEW, TB>>>(nullptr, out);
    k_bias_relu<<<nbF, TB>>>(out, b2);
}

// round 11
// speedup vs baseline: 1.4516x; 1.0252x over previous
#include <cuda_runtime.h>
#include <cuda_bf16.h>
#include <cstdint>

#define NN 50000
#define NE 600000
#define DI 128
#define DH 256

// ---------------- scratch (device globals; referenced ONLY in device code) --
__device__ int g_is64;                                     // 1 if indices are int64
__device__ __align__(16) float g_dinv[NN];                 // deg, then rsqrt(deg)
__device__ __align__(16) int   g_cnt[NN];                  // in-degree counts
__device__ __align__(16) int   g_off[NN + 1];              // CSR offsets
__device__ __align__(16) int   g_cur[NN];                  // scatter cursors
__device__ __align__(16) int2  g_rc[NE];                   // packed (row, col)
__device__ __align__(16) float g_coeff[NE];                // dinv[r]*ew*dinv[c]
__device__ __align__(16) int2  g_ecf[NE];                  // sorted {row, coeff-bits}
__device__ __align__(16) float g_agg1[(size_t)NN * DI];    // A_norm @ x
__device__ __align__(16) float g_h[(size_t)NN * DH];       // relu(agg1@W1+b1)
__device__ __align__(16) float g_t[(size_t)NN * DI];       // h @ W2

__device__ __forceinline__ uint32_t smem_u32(const void* p) {
    return (uint32_t)__cvta_generic_to_shared(p);
}

// ---------------- index dtype detection -------------------------------------
__global__ void k_detect(const int* __restrict__ ei32) {
    if (threadIdx.x == 0 && blockIdx.x == 0) {
        int ok = 1;
        for (int i = 0; i < 32; i++)
            if (ei32[2 * i + 1] != 0) ok = 0;
        g_is64 = ok;
    }
}

__device__ __forceinline__ int get_idx(const void* __restrict__ base, long long i) {
    if (g_is64) return (int)((const long long*)base)[i];
    return ((const int*)base)[i];
}

// ---------------- init: dinv=1 (self-loop), cnt=0 ---------------------------
__global__ void k_init() {
    int i = blockIdx.x * blockDim.x + threadIdx.x;
    if (i < NN) { g_dinv[i] = 1.0f; g_cnt[i] = 0; }
}

__global__ void k_deg_accum(const void* __restrict__ ei, const float* __restrict__ ew) {
    int e = blockIdx.x * blockDim.x + threadIdx.x;
    if (e < NE) {
        int c = get_idx(ei, (long long)NE + e);
        atomicAdd(&g_dinv[c], ew[e]);
    }
}

__global__ void k_finalize_dinv() {
    int i = blockIdx.x * blockDim.x + threadIdx.x;
    if (i < NN) g_dinv[i] = rsqrtf(g_dinv[i]);
}

// ---------------- per-edge precompute: rc, coeff, histogram -----------------
__global__ void k_prep(const void* __restrict__ ei, const float* __restrict__ ew) {
    int e = blockIdx.x * blockDim.x + threadIdx.x;
    if (e >= NE) return;
    int r = get_idx(ei, e);
    int c = get_idx(ei, (long long)NE + e);
    g_rc[e] = make_int2(r, c);
    g_coeff[e] = g_dinv[r] * ew[e] * g_dinv[c];
    atomicAdd(&g_cnt[c], 1);
}

// ---------------- exclusive scan of g_cnt -> g_off, g_cur (1 block) ---------
__global__ void __launch_bounds__(1024) k_scan() {
    __shared__ int part[1024];
    const int C = (NN + 1023) / 1024;          // 49
    int t = threadIdx.x;
    int base = t * C;
    int s = 0;
    for (int i = 0; i < C; i++) {
        int idx = base + i;
        if (idx < NN) s += g_cnt[idx];
    }
    part[t] = s;
    __syncthreads();
    // Hillis-Steele inclusive scan
    for (int d = 1; d < 1024; d <<= 1) {
        int v = (t >= d) ? part[t - d] : 0;
        __syncthreads();
        part[t] += v;
        __syncthreads();
    }
    int run = part[t] - s;                     // exclusive offset of this chunk
    for (int i = 0; i < C; i++) {
        int idx = base + i;
        if (idx < NN) {
            g_off[idx] = run;
            g_cur[idx] = run;
            run += g_cnt[idx];
        }
    }
    if (t == 1023) g_off[NN] = part[1023];
}

// ---------------- scatter edges into CSR order ------------------------------
__global__ void k_scatter() {
    int e = blockIdx.x * blockDim.x + threadIdx.x;
    if (e >= NE) return;
    int2 rc = g_rc[e];
    int pos = atomicAdd(&g_cur[rc.y], 1);
    g_ecf[pos] = make_int2(rc.x, __float_as_int(g_coeff[e]));
}

// ---------------- CSR aggregation (gather, no atomics) ----------------------
// One warp per node; lane owns one float4 (4 dims). Self-loop fused.
// MODE 0: src = x (param),  dst = g_agg1
// MODE 1: src = g_t,        dst = out (param), + bias + relu
template <int MODE>
__global__ void __launch_bounds__(256) k_agg(const float* __restrict__ xp,
                                             const float* __restrict__ bias,
                                             float* __restrict__ op) {
    int node = (blockIdx.x * blockDim.x + threadIdx.x) >> 5;
    if (node >= NN) return;
    int lane = threadIdx.x & 31;
    const float* src = (MODE == 0) ? xp : (const float*)g_t;
    float*       dst = (MODE == 0) ? (float*)g_agg1 : op;

    float dself = g_dinv[node];
    dself *= dself;
    float4 acc = ((const float4*)(src + (size_t)node * DI))[lane];
    acc.x *= dself; acc.y *= dself; acc.z *= dself; acc.w *= dself;

    int e = g_off[node], end = g_off[node + 1];
    for (; e < end; e++) {
        int2 p = g_ecf[e];                    // broadcast load
        float cf = __int_as_float(p.y);
        float4 v = ((const float4*)(src + (size_t)p.x * DI))[lane];
        acc.x = fmaf(cf, v.x, acc.x);
        acc.y = fmaf(cf, v.y, acc.y);
        acc.z = fmaf(cf, v.z, acc.z);
        acc.w = fmaf(cf, v.w, acc.w);
    }
    if (MODE == 1) {
        float4 bv = ((const float4*)bias)[lane];
        acc.x = fmaxf(acc.x + bv.x, 0.f);
        acc.y = fmaxf(acc.y + bv.y, 0.f);
        acc.z = fmaxf(acc.z + bv.z, 0.f);
        acc.w = fmaxf(acc.w + bv.w, 0.f);
    }
    ((float4*)(dst + (size_t)node * DI))[lane] = acc;
}

// =================== tensor-core GEMM (mma.sync, bf16 3-way split) ==========
// MODE 0: C[g_h] = relu(g_agg1[NN,128] @ W1[128,256] + b1)
// MODE 1: C[g_t] =       g_h[NN,256] @ W2[256,128]

__device__ __forceinline__ void ldsm_x4(uint32_t* r, uint32_t addr) {
    asm volatile("ldmatrix.sync.aligned.m8n8.x4.shared.b16 {%0,%1,%2,%3}, [%4];"
                 : "=r"(r[0]), "=r"(r[1]), "=r"(r[2]), "=r"(r[3]) : "r"(addr));
}

__device__ __forceinline__ void mma16816(float* c, const uint32_t* a, const uint32_t* b) {
    asm volatile(
        "mma.sync.aligned.m16n8k16.row.col.f32.bf16.bf16.f32 "
        "{%0,%1,%2,%3}, {%4,%5,%6,%7}, {%8,%9}, {%0,%1,%2,%3};"
        : "+f"(c[0]), "+f"(c[1]), "+f"(c[2]), "+f"(c[3])
        : "r"(a[0]), "r"(a[1]), "r"(a[2]), "r"(a[3]), "r"(b[0]), "r"(b[1]));
}

#define BK 64
#define SA 72
#define SMEM_MM (4 * 128 * SA * 2)

template <int MODE>
__global__ void __launch_bounds__(256)
k_mm(const float* __restrict__ W, const float* __restrict__ bias) {
    constexpr int Kdim = (MODE == 0) ? DI : DH;
    constexpr int Ndim = (MODE == 0) ? DH : DI;
    const float* A = (MODE == 0) ? (const float*)g_agg1 : (const float*)g_h;
    float*       C = (MODE == 0) ? (float*)g_h : (float*)g_t;

    extern __shared__ __nv_bfloat16 sm[];
    __nv_bfloat16* Ah = sm;
    __nv_bfloat16* Al = sm + 128 * SA;
    __nv_bfloat16* Bh = sm + 2 * 128 * SA;
    __nv_bfloat16* Bl = sm + 3 * 128 * SA;

    int tid = threadIdx.x, lane = tid & 31, wid = tid >> 5;
    int mw = wid >> 2, nw = wid & 3;
    int rowBase = blockIdx.y * 128;
    int n0 = blockIdx.x * 128;

    float acc[4][4][4];
#pragma unroll
    for (int i = 0; i < 4; i++)
#pragma unroll
        for (int j = 0; j < 4; j++)
#pragma unroll
            for (int q = 0; q < 4; q++) acc[i][j][q] = 0.0f;

    uint32_t smbA = smem_u32(Ah);
    uint32_t smbAl = smem_u32(Al);
    uint32_t smbB = smem_u32(Bh);
    uint32_t smbBl = smem_u32(Bl);

    int a_row_l = ((lane >> 3) & 1) * 8 + (lane & 7);
    int a_k_l   = (lane >> 4) * 8;
    int b_n_l   = (lane >> 4) * 8 + (lane & 7);
    int b_k_l   = ((lane >> 3) & 1) * 8;

    for (int ch = 0; ch < Kdim / BK; ch++) {
        int k0 = ch * BK;
        if (ch) __syncthreads();
#pragma unroll
        for (int it = 0; it < 8; it++) {
            int idx = it * 256 + tid;
            int r  = idx >> 4;
            int c4 = (idx & 15) * 4;
            int gr = rowBase + r;
            float4 v = make_float4(0.f, 0.f, 0.f, 0.f);
            if (gr < NN) v = *(const float4*)(A + (size_t)gr * Kdim + k0 + c4);
            __nv_bfloat16 hx = __float2bfloat16_rn(v.x);
            __nv_bfloat16 hy = __float2bfloat16_rn(v.y);
            __nv_bfloat16 hz = __float2bfloat16_rn(v.z);
            __nv_bfloat16 hw = __float2bfloat16_rn(v.w);
            __nv_bfloat16 lx = __float2bfloat16_rn(v.x - __bfloat162float(hx));
            __nv_bfloat16 ly = __float2bfloat16_rn(v.y - __bfloat162float(hy));
            __nv_bfloat16 lz = __float2bfloat16_rn(v.z - __bfloat162float(hz));
            __nv_bfloat16 lw = __float2bfloat16_rn(v.w - __bfloat162float(hw));
            int o = r * SA + c4;
            *(__nv_bfloat162*)(Ah + o)     = __halves2bfloat162(hx, hy);
            *(__nv_bfloat162*)(Ah + o + 2) = __halves2bfloat162(hz, hw);
            *(__nv_bfloat162*)(Al + o)     = __halves2bfloat162(lx, ly);
            *(__nv_bfloat162*)(Al + o + 2) = __halves2bfloat162(lz, lw);
        }
#pragma unroll
        for (int it = 0; it < 32; it++) {
            int idx = it * 256 + tid;
            int k = idx >> 7;
            int n = idx & 127;
            float w = W[(size_t)(k0 + k) * Ndim + n0 + n];
            __nv_bfloat16 h = __float2bfloat16_rn(w);
            __nv_bfloat16 l = __float2bfloat16_rn(w - __bfloat162float(h));
            Bh[n * SA + k] = h;
            Bl[n * SA + k] = l;
        }
        __syncthreads();

#pragma unroll
        for (int s = 0; s < 4; s++) {
            uint32_t aH[4][4], aL[4][4], bH[2][4], bL[2][4];
#pragma unroll
            for (int i = 0; i < 4; i++) {
                int row = mw * 64 + i * 16 + a_row_l;
                int kk  = s * 16 + a_k_l;
                uint32_t off = (uint32_t)(row * SA + kk) * 2;
                ldsm_x4(aH[i], smbA + off);
                ldsm_x4(aL[i], smbAl + off);
            }
#pragma unroll
            for (int p = 0; p < 2; p++) {
                int n = nw * 32 + p * 16 + b_n_l;
                int kk = s * 16 + b_k_l;
                uint32_t off = (uint32_t)(n * SA + kk) * 2;
                ldsm_x4(bH[p], smbB + off);
                ldsm_x4(bL[p], smbBl + off);
            }
#pragma unroll
            for (int i = 0; i < 4; i++)
#pragma unroll
                for (int j = 0; j < 4; j++) {
                    int p = j >> 1, o = (j & 1) * 2;
                    mma16816(acc[i][j], aH[i], &bH[p][o]);
                    mma16816(acc[i][j], aH[i], &bL[p][o]);
                    mma16816(acc[i][j], aL[i], &bH[p][o]);
                }
        }
    }

#pragma unroll
    for (int i = 0; i < 4; i++) {
        int r0 = rowBase + mw * 64 + i * 16 + (lane >> 2);
#pragma unroll
        for (int j = 0; j < 4; j++) {
            int gc = n0 + nw * 32 + j * 8 + (lane & 3) * 2;
            float2 v0 = make_float2(acc[i][j][0], acc[i][j][1]);
            float2 v1 = make_float2(acc[i][j][2], acc[i][j][3]);
            if (MODE == 0) {
                float2 bv = *(const float2*)(bias + gc);
                v0.x = fmaxf(v0.x + bv.x, 0.f);
                v0.y = fmaxf(v0.y + bv.y, 0.f);
                v1.x = fmaxf(v1.x + bv.x, 0.f);
                v1.y = fmaxf(v1.y + bv.y, 0.f);
            }
            if (r0 < NN)     *(float2*)(C + (size_t)r0 * Ndim + gc)       = v0;
            if (r0 + 8 < NN) *(float2*)(C + (size_t)(r0 + 8) * Ndim + gc) = v1;
        }
    }
}

// ---------------- launch ----------------------------------------------------
extern "C" void kernel_launch(void* const* d_in, const int* in_sizes, int n_in,
                              void* d_out, int out_size) {
    const float* x   = (const float*)d_in[0];
    const void*  ei  = d_in[1];                 // [2, NE], int32 or int64
    const float* ew  = (const float*)d_in[2];
    const float* W1  = (const float*)d_in[3];
    const float* b1  = (const float*)d_in[4];
    const float* W2  = (const float*)d_in[5];
    const float* b2  = (const float*)d_in[6];
    float*       out = (float*)d_out;

    static bool attr_done = false;
    if (!attr_done) {
        cudaFuncSetAttribute(k_mm<0>, cudaFuncAttributeMaxDynamicSharedMemorySize, SMEM_MM);
        cudaFuncSetAttribute(k_mm<1>, cudaFuncAttributeMaxDynamicSharedMemorySize, SMEM_MM);
        attr_done = true;
    }

    const int TB = 256;
    int nbN  = (NN + TB - 1) / TB;
    int nbE  = (NE + TB - 1) / TB;
    int nbA  = ((long long)NN * 32 + TB - 1) / TB;
    int nbM  = (NN + 127) / 128;

    k_detect<<<1, 32>>>((const int*)ei);

    // degree, dinv, per-edge coeffs, CSR transpose (shared by both layers)
    k_init<<<nbN, TB>>>();
    k_deg_accum<<<nbE, TB>>>(ei, ew);
    k_finalize_dinv<<<nbN, TB>>>();
    k_prep<<<nbE, TB>>>(ei, ew);
    k_scan<<<1, 1024>>>();
    k_scatter<<<nbE, TB>>>();

    // layer 1: g_agg1 = A_norm @ x ; g_h = relu(g_agg1 @ W1 + b1)
    k_agg<0><<<nbA, TB>>>(x, nullptr, nullptr);
    k_mm<0><<<dim3(2, nbM), TB, SMEM_MM>>>(W1, b1);

    // layer 2: g_t = g_h @ W2 ; out = relu(A_norm @ g_t + b2)
    k_mm<1><<<dim3(1, nbM), TB, SMEM_MM>>>(W2, nullptr);
    k_agg<1><<<nbA, TB>>>(nullptr, b2, out);
}

// round 12
// speedup vs baseline: 2.1733x; 1.4972x over previous
#include <cuda_runtime.h>
#include <cuda_bf16.h>
#include <cstdint>

#define NN 50000
#define NE 600000
#define DI 128
#define DH 256

// ---------------- scratch (device globals; referenced ONLY in device code) --
__device__ int g_is64;
__device__ __align__(16) float g_dinv[NN];
__device__ __align__(16) int   g_cnt[NN];
__device__ __align__(16) int   g_off[NN + 1];
__device__ __align__(16) int   g_cur[NN];
__device__ __align__(16) int   g_bsum[256];
__device__ __align__(16) int2  g_rc[NE];
__device__ __align__(16) float g_coeff[NE];
__device__ __align__(16) int2  g_ecf[NE];                       // CSR {row, coeff}
__device__ __align__(16) __nv_bfloat16 g_a1h[(size_t)NN * DI];  // split(A@x)
__device__ __align__(16) __nv_bfloat16 g_a1l[(size_t)NN * DI];
__device__ __align__(16) __nv_bfloat16 g_hh[(size_t)NN * DH];   // split(h)
__device__ __align__(16) __nv_bfloat16 g_hl[(size_t)NN * DH];
__device__ __align__(16) float g_t[(size_t)NN * DI];            // h @ W2
__device__ __align__(16) __nv_bfloat16 g_w1t_h[DI * DH];        // W1^T split [256][128]
__device__ __align__(16) __nv_bfloat16 g_w1t_l[DI * DH];
__device__ __align__(16) __nv_bfloat16 g_w2t_h[DI * DH];        // W2^T split [128][256]
__device__ __align__(16) __nv_bfloat16 g_w2t_l[DI * DH];

__device__ __forceinline__ uint32_t smem_u32(const void* p) {
    return (uint32_t)__cvta_generic_to_shared(p);
}

// ---------------- index dtype detection -------------------------------------
__global__ void k_detect(const int* __restrict__ ei32) {
    if (threadIdx.x == 0 && blockIdx.x == 0) {
        int ok = 1;
        for (int i = 0; i < 32; i++)
            if (ei32[2 * i + 1] != 0) ok = 0;
        g_is64 = ok;
    }
}

__device__ __forceinline__ int get_idx(const void* __restrict__ base, long long i) {
    if (g_is64) return (int)((const long long*)base)[i];
    return ((const int*)base)[i];
}

// ---------------- W pre-transpose + split (once per replay, tiny) -----------
__global__ void k_wsplit(const float* __restrict__ W1, const float* __restrict__ W2) {
    int i = blockIdx.x * blockDim.x + threadIdx.x;
    if (i >= DI * DH) return;
    {   // W1 [128][256] -> [n=256][k=128]
        int n = i >> 7, k = i & 127;
        float w = W1[k * DH + n];
        __nv_bfloat16 h = __float2bfloat16_rn(w);
        g_w1t_h[i] = h;
        g_w1t_l[i] = __float2bfloat16_rn(w - __bfloat162float(h));
    }
    {   // W2 [256][128] -> [n=128][k=256]
        int n = i >> 8, k = i & 255;
        float w = W2[k * DI + n];
        __nv_bfloat16 h = __float2bfloat16_rn(w);
        g_w2t_h[i] = h;
        g_w2t_l[i] = __float2bfloat16_rn(w - __bfloat162float(h));
    }
}

// ---------------- degree / dinv --------------------------------------------
__global__ void k_init() {
    int i = blockIdx.x * blockDim.x + threadIdx.x;
    if (i < NN) { g_dinv[i] = 1.0f; g_cnt[i] = 0; }
}

__global__ void k_deg_accum(const void* __restrict__ ei, const float* __restrict__ ew) {
    int e = blockIdx.x * blockDim.x + threadIdx.x;
    if (e < NE) {
        int c = get_idx(ei, (long long)NE + e);
        atomicAdd(&g_dinv[c], ew[e]);
    }
}

__global__ void k_finalize_dinv() {
    int i = blockIdx.x * blockDim.x + threadIdx.x;
    if (i < NN) g_dinv[i] = rsqrtf(g_dinv[i]);
}

// ---------------- per-edge precompute ---------------------------------------
__global__ void k_prep(const void* __restrict__ ei, const float* __restrict__ ew) {
    int e = blockIdx.x * blockDim.x + threadIdx.x;
    if (e >= NE) return;
    int r = get_idx(ei, e);
    int c = get_idx(ei, (long long)NE + e);
    g_rc[e] = make_int2(r, c);
    g_coeff[e] = g_dinv[r] * ew[e] * g_dinv[c];
    atomicAdd(&g_cnt[c], 1);
}

// ---------------- 3-pass exclusive scan of g_cnt -> g_off, g_cur ------------
__global__ void __launch_bounds__(256) k_scan1() {
    __shared__ int s[256];
    int t = threadIdx.x;
    int i = blockIdx.x * 256 + t;
    s[t] = (i < NN) ? g_cnt[i] : 0;
    __syncthreads();
    for (int d = 128; d > 0; d >>= 1) {
        if (t < d) s[t] += s[t + d];
        __syncthreads();
    }
    if (t == 0) g_bsum[blockIdx.x] = s[0];
}

__global__ void __launch_bounds__(256) k_scan2(int nblk) {
    __shared__ int s[256];
    int t = threadIdx.x;
    int v = (t < nblk) ? g_bsum[t] : 0;
    s[t] = v;
    __syncthreads();
    for (int d = 1; d < 256; d <<= 1) {
        int u = (t >= d) ? s[t - d] : 0;
        __syncthreads();
        s[t] += u;
        __syncthreads();
    }
    if (t < nblk) g_bsum[t] = s[t] - v;       // exclusive
    if (t == 255) g_off[NN] = s[255];          // total
}

__global__ void __launch_bounds__(256) k_scan3() {
    __shared__ int s[256];
    int t = threadIdx.x;
    int i = blockIdx.x * 256 + t;
    int c = (i < NN) ? g_cnt[i] : 0;
    s[t] = c;
    __syncthreads();
    for (int d = 1; d < 256; d <<= 1) {
        int u = (t >= d) ? s[t - d] : 0;
        __syncthreads();
        s[t] += u;
        __syncthreads();
    }
    int off = g_bsum[blockIdx.x] + s[t] - c;
    if (i < NN) { g_off[i] = off; g_cur[i] = off; }
}

__global__ void k_scatter() {
    int e = blockIdx.x * blockDim.x + threadIdx.x;
    if (e >= NE) return;
    int2 rc = g_rc[e];
    int pos = atomicAdd(&g_cur[rc.y], 1);
    g_ecf[pos] = make_int2(rc.x, __float_as_int(g_coeff[e]));
}

// ---------------- CSR aggregation (gather) ----------------------------------
// One warp per node; lane owns one float4. Unroll-2 for MLP.
// MODE 0: src = x (param),  dst = split bf16 g_a1h/g_a1l
// MODE 1: src = g_t,        dst = out (param), + bias + relu
template <int MODE>
__global__ void __launch_bounds__(256) k_agg(const float* __restrict__ xp,
                                             const float* __restrict__ bias,
                                             float* __restrict__ op) {
    int node = (blockIdx.x * blockDim.x + threadIdx.x) >> 5;
    if (node >= NN) return;
    int lane = threadIdx.x & 31;
    const float* src = (MODE == 0) ? xp : (const float*)g_t;

    float dself = g_dinv[node];
    dself *= dself;
    float4 acc = ((const float4*)(src + (size_t)node * DI))[lane];
    acc.x *= dself; acc.y *= dself; acc.z *= dself; acc.w *= dself;

    int e = g_off[node], end = g_off[node + 1];
    for (; e + 2 <= end; e += 2) {
        int2 p0 = g_ecf[e];
        int2 p1 = g_ecf[e + 1];
        float c0 = __int_as_float(p0.y);
        float c1 = __int_as_float(p1.y);
        float4 v0 = ((const float4*)(src + (size_t)p0.x * DI))[lane];
        float4 v1 = ((const float4*)(src + (size_t)p1.x * DI))[lane];
        acc.x = fmaf(c0, v0.x, acc.x); acc.y = fmaf(c0, v0.y, acc.y);
        acc.z = fmaf(c0, v0.z, acc.z); acc.w = fmaf(c0, v0.w, acc.w);
        acc.x = fmaf(c1, v1.x, acc.x); acc.y = fmaf(c1, v1.y, acc.y);
        acc.z = fmaf(c1, v1.z, acc.z); acc.w = fmaf(c1, v1.w, acc.w);
    }
    if (e < end) {
        int2 p = g_ecf[e];
        float cf = __int_as_float(p.y);
        float4 v = ((const float4*)(src + (size_t)p.x * DI))[lane];
        acc.x = fmaf(cf, v.x, acc.x); acc.y = fmaf(cf, v.y, acc.y);
        acc.z = fmaf(cf, v.z, acc.z); acc.w = fmaf(cf, v.w, acc.w);
    }

    if (MODE == 0) {
        __nv_bfloat16 hx = __float2bfloat16_rn(acc.x);
        __nv_bfloat16 hy = __float2bfloat16_rn(acc.y);
        __nv_bfloat16 hz = __float2bfloat16_rn(acc.z);
        __nv_bfloat16 hw = __float2bfloat16_rn(acc.w);
        __nv_bfloat16 lx = __float2bfloat16_rn(acc.x - __bfloat162float(hx));
        __nv_bfloat16 ly = __float2bfloat16_rn(acc.y - __bfloat162float(hy));
        __nv_bfloat16 lz = __float2bfloat16_rn(acc.z - __bfloat162float(hz));
        __nv_bfloat16 lw = __float2bfloat16_rn(acc.w - __bfloat162float(hw));
        size_t o = (size_t)node * DI + lane * 4;
        ((__nv_bfloat162*)(g_a1h + o))[0] = __halves2bfloat162(hx, hy);
        ((__nv_bfloat162*)(g_a1h + o))[1] = __halves2bfloat162(hz, hw);
        ((__nv_bfloat162*)(g_a1l + o))[0] = __halves2bfloat162(lx, ly);
        ((__nv_bfloat162*)(g_a1l + o))[1] = __halves2bfloat162(lz, lw);
    } else {
        float4 bv = ((const float4*)bias)[lane];
        acc.x = fmaxf(acc.x + bv.x, 0.f);
        acc.y = fmaxf(acc.y + bv.y, 0.f);
        acc.z = fmaxf(acc.z + bv.z, 0.f);
        acc.w = fmaxf(acc.w + bv.w, 0.f);
        ((float4*)(op + (size_t)node * DI))[lane] = acc;
    }
}

// =================== tensor-core GEMM (mma.sync, pre-split bf16) ============
// MODE 0: split(g_h) = relu(split_a1 @ W1 + b1)   K=128 (1 chunk), N=256
// MODE 1: g_t        = split_h @ W2               K=256 (2 chunks), N=128
// Fills are pure uint4 copies of pre-split bf16; conversion lives upstream.

__device__ __forceinline__ void ldsm_x4(uint32_t* r, uint32_t addr) {
    asm volatile("ldmatrix.sync.aligned.m8n8.x4.shared.b16 {%0,%1,%2,%3}, [%4];"
                 : "=r"(r[0]), "=r"(r[1]), "=r"(r[2]), "=r"(r[3]) : "r"(addr));
}

__device__ __forceinline__ void mma16816(float* c, const uint32_t* a, const uint32_t* b) {
    asm volatile(
        "mma.sync.aligned.m16n8k16.row.col.f32.bf16.bf16.f32 "
        "{%0,%1,%2,%3}, {%4,%5,%6,%7}, {%8,%9}, {%0,%1,%2,%3};"
        : "+f"(c[0]), "+f"(c[1]), "+f"(c[2]), "+f"(c[3])
        : "r"(a[0]), "r"(a[1]), "r"(a[2]), "r"(a[3]), "r"(b[0]), "r"(b[1]));
}

#define BK 128
#define SA 136  // bf16 row stride (BK + 8): 272B rows -> conflict-free ldmatrix
#define SMEM_MM (4 * 128 * SA * 2)   // Ah, Al, Bh, Bl = 139264 B

template <int MODE>
__global__ void __launch_bounds__(256)
k_mm(const float* __restrict__ bias) {
    constexpr int Kdim = (MODE == 0) ? DI : DH;
    constexpr int Ndim = (MODE == 0) ? DH : DI;
    const __nv_bfloat16* Ah_src = (MODE == 0) ? g_a1h : g_hh;
    const __nv_bfloat16* Al_src = (MODE == 0) ? g_a1l : g_hl;
    const __nv_bfloat16* Bh_src = (MODE == 0) ? g_w1t_h : g_w2t_h;
    const __nv_bfloat16* Bl_src = (MODE == 0) ? g_w1t_l : g_w2t_l;

    extern __shared__ __nv_bfloat16 sm[];
    __nv_bfloat16* Ah = sm;
    __nv_bfloat16* Al = sm + 128 * SA;
    __nv_bfloat16* Bh = sm + 2 * 128 * SA;
    __nv_bfloat16* Bl = sm + 3 * 128 * SA;

    int tid = threadIdx.x, lane = tid & 31, wid = tid >> 5;
    int mw = wid >> 2, nw = wid & 3;
    int rowBase = blockIdx.y * 128;
    int n0 = blockIdx.x * 128;

    float acc[4][4][4];
#pragma unroll
    for (int i = 0; i < 4; i++)
#pragma unroll
        for (int j = 0; j < 4; j++)
#pragma unroll
            for (int q = 0; q < 4; q++) acc[i][j][q] = 0.0f;

    uint32_t smbA = smem_u32(Ah);
    uint32_t smbAl = smem_u32(Al);
    uint32_t smbB = smem_u32(Bh);
    uint32_t smbBl = smem_u32(Bl);

    int a_row_l = ((lane >> 3) & 1) * 8 + (lane & 7);
    int a_k_l   = (lane >> 4) * 8;
    int b_n_l   = (lane >> 4) * 8 + (lane & 7);
    int b_k_l   = ((lane >> 3) & 1) * 8;

#pragma unroll
    for (int ch = 0; ch < Kdim / BK; ch++) {
        int k0 = ch * BK;
        if (ch) __syncthreads();
        // ---- fill A (plain copies), 128 rows x 128 k ----
#pragma unroll
        for (int it = 0; it < 8; it++) {
            int idx = it * 256 + tid;          // 2048 uint4 per tile
            int r  = idx >> 4;
            int c8 = (idx & 15) * 8;
            int gr = rowBase + r;
            uint4 vh = make_uint4(0, 0, 0, 0), vl = make_uint4(0, 0, 0, 0);
            if (gr < NN) {
                vh = *(const uint4*)(Ah_src + (size_t)gr * Kdim + k0 + c8);
                vl = *(const uint4*)(Al_src + (size_t)gr * Kdim + k0 + c8);
            }
            *(uint4*)(Ah + r * SA + c8) = vh;
            *(uint4*)(Al + r * SA + c8) = vl;
        }
        // ---- fill B (plain copies), [n][k] pre-transposed ----
#pragma unroll
        for (int it = 0; it < 8; it++) {
            int idx = it * 256 + tid;
            int n  = idx >> 4;
            int c8 = (idx & 15) * 8;
            *(uint4*)(Bh + n * SA + c8) =
                *(const uint4*)(Bh_src + (size_t)(n0 + n) * Kdim + k0 + c8);
            *(uint4*)(Bl + n * SA + c8) =
                *(const uint4*)(Bl_src + (size_t)(n0 + n) * Kdim + k0 + c8);
        }
        __syncthreads();

        // ---- 8 K-steps of 16 ----
#pragma unroll
        for (int s = 0; s < 8; s++) {
            uint32_t aH[4][4], aL[4][4], bH[2][4], bL[2][4];
#pragma unroll
            for (int i = 0; i < 4; i++) {
                int row = mw * 64 + i * 16 + a_row_l;
                int kk  = s * 16 + a_k_l;
                uint32_t off = (uint32_t)(row * SA + kk) * 2;
                ldsm_x4(aH[i], smbA + off);
                ldsm_x4(aL[i], smbAl + off);
            }
#pragma unroll
            for (int p = 0; p < 2; p++) {
                int n = nw * 32 + p * 16 + b_n_l;
                int kk = s * 16 + b_k_l;
                uint32_t off = (uint32_t)(n * SA + kk) * 2;
                ldsm_x4(bH[p], smbB + off);
                ldsm_x4(bL[p], smbBl + off);
            }
#pragma unroll
            for (int i = 0; i < 4; i++)
#pragma unroll
                for (int j = 0; j < 4; j++) {
                    int p = j >> 1, o = (j & 1) * 2;
                    mma16816(acc[i][j], aH[i], &bH[p][o]);
                    mma16816(acc[i][j], aH[i], &bL[p][o]);
                    mma16816(acc[i][j], aL[i], &bH[p][o]);
                }
        }
    }

    // ---- epilogue ----
#pragma unroll
    for (int i = 0; i < 4; i++) {
        int r0 = rowBase + mw * 64 + i * 16 + (lane >> 2);
#pragma unroll
        for (int j = 0; j < 4; j++) {
            int gc = n0 + nw * 32 + j * 8 + (lane & 3) * 2;
            float2 v0 = make_float2(acc[i][j][0], acc[i][j][1]);
            float2 v1 = make_float2(acc[i][j][2], acc[i][j][3]);
            if (MODE == 0) {
                float2 bv = *(const float2*)(bias + gc);
                v0.x = fmaxf(v0.x + bv.x, 0.f);
                v0.y = fmaxf(v0.y + bv.y, 0.f);
                v1.x = fmaxf(v1.x + bv.x, 0.f);
                v1.y = fmaxf(v1.y + bv.y, 0.f);
                // split-store h
                if (r0 < NN) {
                    __nv_bfloat16 hx = __float2bfloat16_rn(v0.x);
                    __nv_bfloat16 hy = __float2bfloat16_rn(v0.y);
                    size_t o = (size_t)r0 * Ndim + gc;
                    *(__nv_bfloat162*)(g_hh + o) = __halves2bfloat162(hx, hy);
                    *(__nv_bfloat162*)(g_hl + o) = __halves2bfloat162(
                        __float2bfloat16_rn(v0.x - __bfloat162float(hx)),
                        __float2bfloat16_rn(v0.y - __bfloat162float(hy)));
                }
                if (r0 + 8 < NN) {
                    __nv_bfloat16 hx = __float2bfloat16_rn(v1.x);
                    __nv_bfloat16 hy = __float2bfloat16_rn(v1.y);
                    size_t o = (size_t)(r0 + 8) * Ndim + gc;
                    *(__nv_bfloat162*)(g_hh + o) = __halves2bfloat162(hx, hy);
                    *(__nv_bfloat162*)(g_hl + o) = __halves2bfloat162(
                        __float2bfloat16_rn(v1.x - __bfloat162float(hx)),
                        __float2bfloat16_rn(v1.y - __bfloat162float(hy)));
                }
            } else {
                if (r0 < NN)     *(float2*)(g_t + (size_t)r0 * Ndim + gc)       = v0;
                if (r0 + 8 < NN) *(float2*)(g_t + (size_t)(r0 + 8) * Ndim + gc) = v1;
            }
        }
    }
}

// ---------------- launch ----------------------------------------------------
extern "C" void kernel_launch(void* const* d_in, const int* in_sizes, int n_in,
                              void* d_out, int out_size) {
    const float* x   = (const float*)d_in[0];
    const void*  ei  = d_in[1];                 // [2, NE], int32 or int64
    const float* ew  = (const float*)d_in[2];
    const float* W1  = (const float*)d_in[3];
    const float* b1  = (const float*)d_in[4];
    const float* W2  = (const float*)d_in[5];
    const float* b2  = (const float*)d_in[6];
    float*       out = (float*)d_out;

    static bool attr_done = false;
    if (!attr_done) {
        cudaFuncSetAttribute(k_mm<0>, cudaFuncAttributeMaxDynamicSharedMemorySize, SMEM_MM);
        cudaFuncSetAttribute(k_mm<1>, cudaFuncAttributeMaxDynamicSharedMemorySize, SMEM_MM);
        attr_done = true;
    }

    const int TB = 256;
    int nbN  = (NN + TB - 1) / TB;              // 196
    int nbE  = (NE + TB - 1) / TB;
    int nbA  = ((long long)NN * 32 + TB - 1) / TB;
    int nbM  = (NN + 127) / 128;
    int nbW  = (DI * DH + TB - 1) / TB;

    k_detect<<<1, 32>>>((const int*)ei);
    k_wsplit<<<nbW, TB>>>(W1, W2);

    // degree, dinv, per-edge coeffs, CSR transpose
    k_init<<<nbN, TB>>>();
    k_deg_accum<<<nbE, TB>>>(ei, ew);
    k_finalize_dinv<<<nbN, TB>>>();
    k_prep<<<nbE, TB>>>(ei, ew);
    k_scan1<<<nbN, TB>>>();
    k_scan2<<<1, 256>>>(nbN);
    k_scan3<<<nbN, TB>>>();
    k_scatter<<<nbE, TB>>>();

    // layer 1
    k_agg<0><<<nbA, TB>>>(x, nullptr, nullptr);
    k_mm<0><<<dim3(2, nbM), TB, SMEM_MM>>>(b1);

    // layer 2
    k_mm<1><<<dim3(1, nbM), TB, SMEM_MM>>>(nullptr);
    k_agg<1><<<nbA, TB>>>(nullptr, b2, out);
}

// round 15
// speedup vs baseline: 2.2974x; 1.0571x over previous
#include <cuda_runtime.h>
#include <cuda_bf16.h>
#include <cstdint>

#define NN 50000
#define NE 600000
#define DI 128
#define DH 256

// ---------------- scratch (device globals; referenced ONLY in device code) --
__device__ int g_is64;
__device__ __align__(16) float g_dinv[NN];
__device__ __align__(16) int   g_cnt[NN];
__device__ __align__(16) int   g_off[NN + 1];
__device__ __align__(16) int   g_cur[NN];
__device__ __align__(16) int   g_bsum[256];
__device__ __align__(16) int2  g_rc[NE];
__device__ __align__(16) int2  g_ecf[NE];                       // CSR {row, coeff}
__device__ __align__(16) __nv_bfloat16 g_a1h[(size_t)NN * DI];  // split(A@x)
__device__ __align__(16) __nv_bfloat16 g_a1l[(size_t)NN * DI];
__device__ __align__(16) __nv_bfloat16 g_hh[(size_t)NN * DH];   // split(h)
__device__ __align__(16) __nv_bfloat16 g_hl[(size_t)NN * DH];
__device__ __align__(16) float g_t[(size_t)NN * DI];            // h @ W2
__device__ __align__(16) __nv_bfloat16 g_w1t_h[DI * DH];        // W1^T split [256][128]
__device__ __align__(16) __nv_bfloat16 g_w1t_l[DI * DH];
__device__ __align__(16) __nv_bfloat16 g_w2t_h[DI * DH];        // W2^T split [128][256]
__device__ __align__(16) __nv_bfloat16 g_w2t_l[DI * DH];

__device__ __forceinline__ uint32_t smem_u32(const void* p) {
    return (uint32_t)__cvta_generic_to_shared(p);
}

// ---------------- index dtype detection -------------------------------------
__global__ void k_detect(const int* __restrict__ ei32) {
    if (threadIdx.x == 0 && blockIdx.x == 0) {
        int ok = 1;
        for (int i = 0; i < 32; i++)
            if (ei32[2 * i + 1] != 0) ok = 0;
        g_is64 = ok;
    }
}

__device__ __forceinline__ int get_idx(const void* __restrict__ base, long long i) {
    if (g_is64) return (int)((const long long*)base)[i];
    return ((const int*)base)[i];
}

// ---------------- init (dinv=1, cnt=0) + W transpose/split, fused -----------
__global__ void k_init_wsplit(const float* __restrict__ W1, const float* __restrict__ W2) {
    int i = blockIdx.x * blockDim.x + threadIdx.x;
    if (i < NN) { g_dinv[i] = 1.0f; g_cnt[i] = 0; }
    if (i < DI * DH) {
        {   // W1 [128][256] -> [n=256][k=128]
            int n = i >> 7, k = i & 127;
            float w = W1[k * DH + n];
            __nv_bfloat16 h = __float2bfloat16_rn(w);
            g_w1t_h[i] = h;
            g_w1t_l[i] = __float2bfloat16_rn(w - __bfloat162float(h));
        }
        {   // W2 [256][128] -> [n=128][k=256]
            int n = i >> 8, k = i & 255;
            float w = W2[k * DI + n];
            __nv_bfloat16 h = __float2bfloat16_rn(w);
            g_w2t_h[i] = h;
            g_w2t_l[i] = __float2bfloat16_rn(w - __bfloat162float(h));
        }
    }
}

// ---------------- one edge pass: rc decode + degree + count histogram -------
__global__ void k_pre(const void* __restrict__ ei, const float* __restrict__ ew) {
    int e = blockIdx.x * blockDim.x + threadIdx.x;
    if (e >= NE) return;
    int r = get_idx(ei, e);
    int c = get_idx(ei, (long long)NE + e);
    g_rc[e] = make_int2(r, c);
    atomicAdd(&g_dinv[c], ew[e]);
    atomicAdd(&g_cnt[c], 1);
}

// ---------------- finalize dinv + block-reduce counts (fused) ---------------
__global__ void __launch_bounds__(256) k_fin_scan1() {
    __shared__ int s[256];
    int t = threadIdx.x;
    int i = blockIdx.x * 256 + t;
    if (i < NN) g_dinv[i] = rsqrtf(g_dinv[i]);
    s[t] = (i < NN) ? g_cnt[i] : 0;
    __syncthreads();
    for (int d = 128; d > 0; d >>= 1) {
        if (t < d) s[t] += s[t + d];
        __syncthreads();
    }
    if (t == 0) g_bsum[blockIdx.x] = s[0];
}

__global__ void __launch_bounds__(256) k_scan2(int nblk) {
    __shared__ int s[256];
    int t = threadIdx.x;
    int v = (t < nblk) ? g_bsum[t] : 0;
    s[t] = v;
    __syncthreads();
    for (int d = 1; d < 256; d <<= 1) {
        int u = (t >= d) ? s[t - d] : 0;
        __syncthreads();
        s[t] += u;
        __syncthreads();
    }
    if (t < nblk) g_bsum[t] = s[t] - v;       // exclusive
    if (t == 255) g_off[NN] = s[255];
}

__global__ void __launch_bounds__(256) k_scan3() {
    __shared__ int s[256];
    int t = threadIdx.x;
    int i = blockIdx.x * 256 + t;
    int c = (i < NN) ? g_cnt[i] : 0;
    s[t] = c;
    __syncthreads();
    for (int d = 1; d < 256; d <<= 1) {
        int u = (t >= d) ? s[t - d] : 0;
        __syncthreads();
        s[t] += u;
        __syncthreads();
    }
    int off = g_bsum[blockIdx.x] + s[t] - c;
    if (i < NN) { g_off[i] = off; g_cur[i] = off; }
}

// ---------------- scatter into CSR order; coeff computed here ---------------
__global__ void k_scatter(const float* __restrict__ ew) {
    int e = blockIdx.x * blockDim.x + threadIdx.x;
    if (e >= NE) return;
    int2 rc = g_rc[e];
    float coeff = g_dinv[rc.x] * ew[e] * g_dinv[rc.y];
    int pos = atomicAdd(&g_cur[rc.y], 1);
    g_ecf[pos] = make_int2(rc.x, __float_as_int(coeff));
}

// ---------------- CSR aggregation (gather) ----------------------------------
// One warp per node; lane owns one float4. Unroll-4 for MLP.
// MODE 0: src = x (param),  dst = split bf16 g_a1h/g_a1l
// MODE 1: src = g_t,        dst = out (param), + bias + relu
template <int MODE>
__global__ void __launch_bounds__(256) k_agg(const float* __restrict__ xp,
                                             const float* __restrict__ bias,
                                             float* __restrict__ op) {
    int node = (blockIdx.x * blockDim.x + threadIdx.x) >> 5;
    if (node >= NN) return;
    int lane = threadIdx.x & 31;
    const float* src = (MODE == 0) ? xp : (const float*)g_t;

    float dself = g_dinv[node];
    dself *= dself;
    float4 acc = ((const float4*)(src + (size_t)node * DI))[lane];
    acc.x *= dself; acc.y *= dself; acc.z *= dself; acc.w *= dself;

    int e = g_off[node], end = g_off[node + 1];
    for (; e + 4 <= end; e += 4) {
        int2 p0 = g_ecf[e];
        int2 p1 = g_ecf[e + 1];
        int2 p2 = g_ecf[e + 2];
        int2 p3 = g_ecf[e + 3];
        float4 v0 = ((const float4*)(src + (size_t)p0.x * DI))[lane];
        float4 v1 = ((const float4*)(src + (size_t)p1.x * DI))[lane];
        float4 v2 = ((const float4*)(src + (size_t)p2.x * DI))[lane];
        float4 v3 = ((const float4*)(src + (size_t)p3.x * DI))[lane];
        float c0 = __int_as_float(p0.y), c1 = __int_as_float(p1.y);
        float c2 = __int_as_float(p2.y), c3 = __int_as_float(p3.y);
        acc.x = fmaf(c0, v0.x, acc.x); acc.y = fmaf(c0, v0.y, acc.y);
        acc.z = fmaf(c0, v0.z, acc.z); acc.w = fmaf(c0, v0.w, acc.w);
        acc.x = fmaf(c1, v1.x, acc.x); acc.y = fmaf(c1, v1.y, acc.y);
        acc.z = fmaf(c1, v1.z, acc.z); acc.w = fmaf(c1, v1.w, acc.w);
        acc.x = fmaf(c2, v2.x, acc.x); acc.y = fmaf(c2, v2.y, acc.y);
        acc.z = fmaf(c2, v2.z, acc.z); acc.w = fmaf(c2, v2.w, acc.w);
        acc.x = fmaf(c3, v3.x, acc.x); acc.y = fmaf(c3, v3.y, acc.y);
        acc.z = fmaf(c3, v3.z, acc.z); acc.w = fmaf(c3, v3.w, acc.w);
    }
    for (; e < end; e++) {
        int2 p = g_ecf[e];
        float cf = __int_as_float(p.y);
        float4 v = ((const float4*)(src + (size_t)p.x * DI))[lane];
        acc.x = fmaf(cf, v.x, acc.x); acc.y = fmaf(cf, v.y, acc.y);
        acc.z = fmaf(cf, v.z, acc.z); acc.w = fmaf(cf, v.w, acc.w);
    }

    if (MODE == 0) {
        __nv_bfloat16 hx = __float2bfloat16_rn(acc.x);
        __nv_bfloat16 hy = __float2bfloat16_rn(acc.y);
        __nv_bfloat16 hz = __float2bfloat16_rn(acc.z);
        __nv_bfloat16 hw = __float2bfloat16_rn(acc.w);
        __nv_bfloat16 lx = __float2bfloat16_rn(acc.x - __bfloat162float(hx));
        __nv_bfloat16 ly = __float2bfloat16_rn(acc.y - __bfloat162float(hy));
        __nv_bfloat16 lz = __float2bfloat16_rn(acc.z - __bfloat162float(hz));
        __nv_bfloat16 lw = __float2bfloat16_rn(acc.w - __bfloat162float(hw));
        size_t o = (size_t)node * DI + lane * 4;
        ((__nv_bfloat162*)(g_a1h + o))[0] = __halves2bfloat162(hx, hy);
        ((__nv_bfloat162*)(g_a1h + o))[1] = __halves2bfloat162(hz, hw);
        ((__nv_bfloat162*)(g_a1l + o))[0] = __halves2bfloat162(lx, ly);
        ((__nv_bfloat162*)(g_a1l + o))[1] = __halves2bfloat162(lz, lw);
    } else {
        float4 bv = ((const float4*)bias)[lane];
        acc.x = fmaxf(acc.x + bv.x, 0.f);
        acc.y = fmaxf(acc.y + bv.y, 0.f);
        acc.z = fmaxf(acc.z + bv.z, 0.f);
        acc.w = fmaxf(acc.w + bv.w, 0.f);
        ((float4*)(op + (size_t)node * DI))[lane] = acc;
    }
}

// =================== tensor-core GEMM (mma.sync, pre-split bf16) ============
// MODE 0: split(g_h) = relu(split_a1 @ W1 + b1)   K=128 (1 chunk), N=256
// MODE 1: g_t        = split_h @ W2               K=256 (2 chunks), N=128

__device__ __forceinline__ void ldsm_x4(uint32_t* r, uint32_t addr) {
    asm volatile("ldmatrix.sync.aligned.m8n8.x4.shared.b16 {%0,%1,%2,%3}, [%4];"
                 : "=r"(r[0]), "=r"(r[1]), "=r"(r[2]), "=r"(r[3]) : "r"(addr));
}

__device__ __forceinline__ void mma16816(float* c, const uint32_t* a, const uint32_t* b) {
    asm volatile(
        "mma.sync.aligned.m16n8k16.row.col.f32.bf16.bf16.f32 "
        "{%0,%1,%2,%3}, {%4,%5,%6,%7}, {%8,%9}, {%0,%1,%2,%3};"
        : "+f"(c[0]), "+f"(c[1]), "+f"(c[2]), "+f"(c[3])
        : "r"(a[0]), "r"(a[1]), "r"(a[2]), "r"(a[3]), "r"(b[0]), "r"(b[1]));
}

#define BK 128
#define SA 136  // bf16 row stride (BK + 8): conflict-free ldmatrix
#define SMEM_MM (4 * 128 * SA * 2)   // Ah, Al, Bh, Bl = 139264 B

template <int MODE>
__global__ void __launch_bounds__(256)
k_mm(const float* __restrict__ bias) {
    constexpr int Kdim = (MODE == 0) ? DI : DH;
    constexpr int Ndim = (MODE == 0) ? DH : DI;
    const __nv_bfloat16* Ah_src = (MODE == 0) ? g_a1h : g_hh;
    const __nv_bfloat16* Al_src = (MODE == 0) ? g_a1l : g_hl;
    const __nv_bfloat16* Bh_src = (MODE == 0) ? g_w1t_h : g_w2t_h;
    const __nv_bfloat16* Bl_src = (MODE == 0) ? g_w1t_l : g_w2t_l;

    extern __shared__ __nv_bfloat16 sm[];
    __nv_bfloat16* Ah = sm;
    __nv_bfloat16* Al = sm + 128 * SA;
    __nv_bfloat16* Bh = sm + 2 * 128 * SA;
    __nv_bfloat16* Bl = sm + 3 * 128 * SA;

    int tid = threadIdx.x, lane = tid & 31, wid = tid >> 5;
    int mw = wid >> 2, nw = wid & 3;
    int rowBase = blockIdx.y * 128;
    int n0 = blockIdx.x * 128;

    float acc[4][4][4];
#pragma unroll
    for (int i = 0; i < 4; i++)
#pragma unroll
        for (int j = 0; j < 4; j++)
#pragma unroll
            for (int q = 0; q < 4; q++) acc[i][j][q] = 0.0f;

    uint32_t smbA = smem_u32(Ah);
    uint32_t smbAl = smem_u32(Al);
    uint32_t smbB = smem_u32(Bh);
    uint32_t smbBl = smem_u32(Bl);

    int a_row_l = ((lane >> 3) & 1) * 8 + (lane & 7);
    int a_k_l   = (lane >> 4) * 8;
    int b_n_l   = (lane >> 4) * 8 + (lane & 7);
    int b_k_l   = ((lane >> 3) & 1) * 8;

#pragma unroll
    for (int ch = 0; ch < Kdim / BK; ch++) {
        int k0 = ch * BK;
        if (ch) __syncthreads();
#pragma unroll
        for (int it = 0; it < 8; it++) {
            int idx = it * 256 + tid;
            int r  = idx >> 4;
            int c8 = (idx & 15) * 8;
            int gr = rowBase + r;
            uint4 vh = make_uint4(0, 0, 0, 0), vl = make_uint4(0, 0, 0, 0);
            if (gr < NN) {
                vh = *(const uint4*)(Ah_src + (size_t)gr * Kdim + k0 + c8);
                vl = *(const uint4*)(Al_src + (size_t)gr * Kdim + k0 + c8);
            }
            *(uint4*)(Ah + r * SA + c8) = vh;
            *(uint4*)(Al + r * SA + c8) = vl;
        }
#pragma unroll
        for (int it = 0; it < 8; it++) {
            int idx = it * 256 + tid;
            int n  = idx >> 4;
            int c8 = (idx & 15) * 8;
            *(uint4*)(Bh + n * SA + c8) =
                *(const uint4*)(Bh_src + (size_t)(n0 + n) * Kdim + k0 + c8);
            *(uint4*)(Bl + n * SA + c8) =
                *(const uint4*)(Bl_src + (size_t)(n0 + n) * Kdim + k0 + c8);
        }
        __syncthreads();

#pragma unroll
        for (int s = 0; s < 8; s++) {
            uint32_t aH[4][4], aL[4][4], bH[2][4], bL[2][4];
#pragma unroll
            for (int i = 0; i < 4; i++) {
                int row = mw * 64 + i * 16 + a_row_l;
                int kk  = s * 16 + a_k_l;
                uint32_t off = (uint32_t)(row * SA + kk) * 2;
                ldsm_x4(aH[i], smbA + off);
                ldsm_x4(aL[i], smbAl + off);
            }
#pragma unroll
            for (int p = 0; p < 2; p++) {
                int n = nw * 32 + p * 16 + b_n_l;
                int kk = s * 16 + b_k_l;
                uint32_t off = (uint32_t)(n * SA + kk) * 2;
                ldsm_x4(bH[p], smbB + off);
                ldsm_x4(bL[p], smbBl + off);
            }
#pragma unroll
            for (int i = 0; i < 4; i++)
#pragma unroll
                for (int j = 0; j < 4; j++) {
                    int p = j >> 1, o = (j & 1) * 2;
                    mma16816(acc[i][j], aH[i], &bH[p][o]);
                    mma16816(acc[i][j], aH[i], &bL[p][o]);
                    mma16816(acc[i][j], aL[i], &bH[p][o]);
                }
        }
    }

    // ---- epilogue ----
#pragma unroll
    for (int i = 0; i < 4; i++) {
        int r0 = rowBase + mw * 64 + i * 16 + (lane >> 2);
#pragma unroll
        for (int j = 0; j < 4; j++) {
            int gc = n0 + nw * 32 + j * 8 + (lane & 3) * 2;
            float2 v0 = make_float2(acc[i][j][0], acc[i][j][1]);
            float2 v1 = make_float2(acc[i][j][2], acc[i][j][3]);
            if (MODE == 0) {
                float2 bv = *(const float2*)(bias + gc);
                v0.x = fmaxf(v0.x + bv.x, 0.f);
                v0.y = fmaxf(v0.y + bv.y, 0.f);
                v1.x = fmaxf(v1.x + bv.x, 0.f);
                v1.y = fmaxf(v1.y + bv.y, 0.f);
                if (r0 < NN) {
                    __nv_bfloat16 hx = __float2bfloat16_rn(v0.x);
                    __nv_bfloat16 hy = __float2bfloat16_rn(v0.y);
                    size_t o = (size_t)r0 * Ndim + gc;
                    *(__nv_bfloat162*)(g_hh + o) = __halves2bfloat162(hx, hy);
                    *(__nv_bfloat162*)(g_hl + o) = __halves2bfloat162(
                        __float2bfloat16_rn(v0.x - __bfloat162float(hx)),
                        __float2bfloat16_rn(v0.y - __bfloat162float(hy)));
                }
                if (r0 + 8 < NN) {
                    __nv_bfloat16 hx = __float2bfloat16_rn(v1.x);
                    __nv_bfloat16 hy = __float2bfloat16_rn(v1.y);
                    size_t o = (size_t)(r0 + 8) * Ndim + gc;
                    *(__nv_bfloat162*)(g_hh + o) = __halves2bfloat162(hx, hy);
                    *(__nv_bfloat162*)(g_hl + o) = __halves2bfloat162(
                        __float2bfloat16_rn(v1.x - __bfloat162float(hx)),
                        __float2bfloat16_rn(v1.y - __bfloat162float(hy)));
                }
            } else {
                if (r0 < NN)     *(float2*)(g_t + (size_t)r0 * Ndim + gc)       = v0;
                if (r0 + 8 < NN) *(float2*)(g_t + (size_t)(r0 + 8) * Ndim + gc) = v1;
            }
        }
    }
}

// ---------------- launch ----------------------------------------------------
extern "C" void kernel_launch(void* const* d_in, const int* in_sizes, int n_in,
                              void* d_out, int out_size) {
    const float* x   = (const float*)d_in[0];
    const void*  ei  = d_in[1];                 // [2, NE], int32 or int64
    const float* ew  = (const float*)d_in[2];
    const float* W1  = (const float*)d_in[3];
    const float* b1  = (const float*)d_in[4];
    const float* W2  = (const float*)d_in[5];
    const float* b2  = (const float*)d_in[6];
    float*       out = (float*)d_out;

    static bool attr_done = false;
    if (!attr_done) {
        cudaFuncSetAttribute(k_mm<0>, cudaFuncAttributeMaxDynamicSharedMemorySize, SMEM_MM);
        cudaFuncSetAttribute(k_mm<1>, cudaFuncAttributeMaxDynamicSharedMemorySize, SMEM_MM);
        attr_done = true;
    }

    const int TB = 256;
    int nbN  = (NN + TB - 1) / TB;              // 196
    int nbE  = (NE + TB - 1) / TB;
    int nbA  = ((long long)NN * 32 + TB - 1) / TB;
    int nbM  = (NN + 127) / 128;

    k_detect<<<1, 32>>>((const int*)ei);
    k_init_wsplit<<<nbN, TB>>>(W1, W2);
    k_pre<<<nbE, TB>>>(ei, ew);
    k_fin_scan1<<<nbN, TB>>>();
    k_scan2<<<1, 256>>>(nbN);
    k_scan3<<<nbN, TB>>>();
    k_scatter<<<nbE, TB>>>(ew);

    // layer 1
    k_agg<0><<<nbA, TB>>>(x, nullptr, nullptr);
    k_mm<0><<<dim3(2, nbM), TB, SMEM_MM>>>(b1);

    // layer 2
    k_mm<1><<<dim3(1, nbM), TB, SMEM_MM>>>(nullptr);
    k_agg<1><<<nbA, TB>>>(nullptr, b2, out);
}